// round 4
// baseline (speedup 1.0000x reference)
#include <cuda_runtime.h>
#include <cuda_bf16.h>
#include <stdint.h>
#include <math.h>

#define N_ITEMS 100000
#define E1N 400000
#define E2N 400000
#define DIM 128
#define N_TGT 40000
#define KC 32

#define ROWB 272          // padded byte stride for 128 bf16 cols (16B-aligned, conflict-free LDSM)
#define BTILE (128 * ROWB) // 34816 bytes per 128x128 bf16 tile

// ---------------- scratch (static device globals; no runtime allocation) ----------------
__device__ float d_ft[(size_t)N_ITEMS * DIM];   // aggregated item features
__device__ float d_g [(size_t)N_ITEMS * DIM];   // ft @ W_q[:128]
__device__ float d_f [(size_t)N_TGT  * DIM];    // concat(h_t, last) @ W_r
__device__ float d_e1[E1N];
__device__ float d_ex[E1N];
__device__ int   d_menc[N_ITEMS];
__device__ float d_z [N_ITEMS];
// prepped bf16 hi/lo images of W_q[128:256] transposed to [n][k], ROWB-padded rows
__device__ __align__(16) unsigned char d_Bh2[BTILE];
__device__ __align__(16) unsigned char d_Bl2[BTILE];

// ---------------- helpers ----------------
__device__ __forceinline__ int fenc(float f) {
    int i = __float_as_int(f);
    return (i >= 0) ? i : (i ^ 0x7FFFFFFF);
}
__device__ __forceinline__ float fdec(int i) {
    return __int_as_float((i >= 0) ? i : (i ^ 0x7FFFFFFF));
}
__device__ __forceinline__ unsigned long long pack2(float lo, float hi) {
    unsigned long long r;
    asm("mov.b64 %0, {%1, %2};" : "=l"(r) : "f"(lo), "f"(hi));
    return r;
}
__device__ __forceinline__ void fma2(unsigned long long &d, unsigned long long a, unsigned long long b) {
    asm("fma.rn.f32x2 %0, %1, %2, %0;" : "+l"(d) : "l"(a), "l"(b));
}
__device__ __forceinline__ float2 unpack2(unsigned long long v) {
    float lo, hi;
    asm("mov.b64 {%0, %1}, %2;" : "=f"(lo), "=f"(hi) : "l"(v));
    return make_float2(lo, hi);
}
__device__ __forceinline__ void red_add_v4(float* p, float4 v) {
    asm volatile("red.global.add.v4.f32 [%0], {%1, %2, %3, %4};"
                 :: "l"(p), "f"(v.x), "f"(v.y), "f"(v.z), "f"(v.w) : "memory");
}
__device__ __forceinline__ uint32_t smem_to_u32(const void* p) {
    uint32_t a;
    asm("{ .reg .u64 t; cvta.to.shared.u64 t, %1; cvt.u32.u64 %0, t; }" : "=r"(a) : "l"(p));
    return a;
}
__device__ __forceinline__ float tanh_fast(float x) {
    float r;
    asm("tanh.approx.f32 %0, %1;" : "=f"(r) : "f"(x));
    return r;
}
__device__ __forceinline__ void ldsm_x4(uint32_t &r0, uint32_t &r1, uint32_t &r2, uint32_t &r3, uint32_t addr) {
    asm volatile("ldmatrix.sync.aligned.m8n8.x4.shared.b16 {%0,%1,%2,%3}, [%4];"
                 : "=r"(r0), "=r"(r1), "=r"(r2), "=r"(r3) : "r"(addr));
}
__device__ __forceinline__ void mma_bf16(float &d0, float &d1, float &d2, float &d3,
                                         uint32_t a0, uint32_t a1, uint32_t a2, uint32_t a3,
                                         uint32_t b0, uint32_t b1) {
    asm volatile("mma.sync.aligned.m16n8k16.row.col.f32.bf16.bf16.f32 "
                 "{%0,%1,%2,%3}, {%4,%5,%6,%7}, {%8,%9}, {%0,%1,%2,%3};"
                 : "+f"(d0), "+f"(d1), "+f"(d2), "+f"(d3)
                 : "r"(a0), "r"(a1), "r"(a2), "r"(a3), "r"(b0), "r"(b1));
}

// ---------------- K0: init accumulators ----------------
__global__ void init_kernel(float* __restrict__ out) {
    int stride = gridDim.x * blockDim.x;
    int i0 = blockIdx.x * blockDim.x + threadIdx.x;
    for (int i = i0; i < N_ITEMS * DIM; i += stride) d_ft[i] = 0.0f;
    for (int i = i0; i < N_TGT * DIM;  i += stride) out[i]  = 0.0f;
    for (int i = i0; i < N_ITEMS;      i += stride) { d_z[i] = 0.0f; d_menc[i] = (int)0x80000000; }
}

// ---------------- prep: bf16 hi/lo of Wq_bot^T into [n][k] ROWB-padded layout ----------------
__global__ void prep_wq_kernel(const float* __restrict__ W_q) {
    int i = blockIdx.x * blockDim.x + threadIdx.x;
    if (i >= DIM * DIM) return;
    int n = i >> 7, k = i & 127;
    float w = W_q[(size_t)(DIM + k) * DIM + n];         // B^T[n][k] = W[128+k][n]
    __nv_bfloat16 hi = __float2bfloat16(w);
    __nv_bfloat16 lo = __float2bfloat16(w - __bfloat162float(hi));
    uint32_t off = (uint32_t)n * ROWB + k * 2;
    *(__nv_bfloat16*)(d_Bh2 + off) = hi;
    *(__nv_bfloat16*)(d_Bl2 + off) = lo;
}

// ---------------- K1: per-edge logit + segment max (warp per edge) ----------------
__global__ __launch_bounds__(256) void edge1_kernel(
    const float* __restrict__ h_v, const float* __restrict__ h_d,
    const float* __restrict__ W_pi, const float* __restrict__ W_M,
    const int* __restrict__ src1, const int* __restrict__ dst1)
{
    int wid = threadIdx.x >> 5, lane = threadIdx.x & 31;
    int e = blockIdx.x * 8 + wid;
    if (e >= E1N) return;
    int s = src1[e], d = dst1[e];
    float4 a  = ((const float4*)(h_v + (size_t)s * DIM))[lane];
    float4 b  = ((const float4*)(h_v + (size_t)d * DIM))[lane];
    float4 h  = ((const float4*)(h_d + (size_t)e * DIM))[lane];
    float4 p  = ((const float4*)W_pi)[lane];
    float4 ma = ((const float4*)W_M)[lane];
    float4 mb = ((const float4*)(W_M + DIM))[lane];
    float4 uv = make_float4(a.x*b.x, a.y*b.y, a.z*b.z, a.w*b.w);
    float d1 = uv.x*h.x*p.x + uv.y*h.y*p.y + uv.z*h.z*p.z + uv.w*h.w*p.w;
    float dm = uv.x*ma.x + uv.y*ma.y + uv.z*ma.z + uv.w*ma.w
             + h.x*mb.x + h.y*mb.y + h.z*mb.z + h.w*mb.w;
    #pragma unroll
    for (int o = 16; o; o >>= 1) {
        d1 += __shfl_xor_sync(0xffffffffu, d1, o);
        dm += __shfl_xor_sync(0xffffffffu, dm, o);
    }
    if (lane == 0) {
        float ev = d1 * (1.0f / (1.0f + expf(-dm)));
        d_e1[e] = ev;
        atomicMax(&d_menc[d], fenc(ev));
    }
}

// ---------------- K2: exp + segment sum (thread per edge) ----------------
__global__ void edge1_softmax_kernel(const int* __restrict__ dst1) {
    int e = blockIdx.x * blockDim.x + threadIdx.x;
    if (e >= E1N) return;
    int d = dst1[e];
    float m = fdec(d_menc[d]);
    float v = expf(d_e1[e] - m);
    d_ex[e] = v;
    atomicAdd(&d_z[d], v);
}

// ---------------- K3: normalize + aggregate ft (4 edges per warp for MLP) ----------------
__global__ __launch_bounds__(256) void edge1_agg_kernel(
    const float* __restrict__ h_v,
    const int* __restrict__ src1, const int* __restrict__ dst1)
{
    int warp = blockIdx.x * 8 + (threadIdx.x >> 5);
    int lane = threadIdx.x & 31;
    int e0 = warp * 4;
    int s[4], d[4];
    #pragma unroll
    for (int i = 0; i < 4; i++) { s[i] = src1[e0 + i]; d[i] = dst1[e0 + i]; }
    float a[4];
    #pragma unroll
    for (int i = 0; i < 4; i++) a[i] = d_ex[e0 + i] / d_z[d[i]];
    float4 v[4];
    #pragma unroll
    for (int i = 0; i < 4; i++) v[i] = ((const float4*)(h_v + (size_t)s[i] * DIM))[lane];
    #pragma unroll
    for (int i = 0; i < 4; i++) {
        v[i].x *= a[i]; v[i].y *= a[i]; v[i].z *= a[i]; v[i].w *= a[i];
        red_add_v4(d_ft + (size_t)d[i] * DIM + lane * 4, v[i]);
    }
}

// ---------------- K4: g = ft @ W_q[:128]  (f32x2 register-tiled GEMM) ----------------
__global__ __launch_bounds__(256) void gemm_g_kernel(const float* __restrict__ W_q) {
    __shared__ __align__(16) float As[KC][132];
    __shared__ __align__(16) float Bs[KC][128];
    int tid = threadIdx.x;
    int ty = tid >> 4, tx = tid & 15;
    int rowBase = blockIdx.x * 128;
    unsigned long long acc[8][4];
    #pragma unroll
    for (int i = 0; i < 8; i++)
        #pragma unroll
        for (int j = 0; j < 4; j++) acc[i][j] = 0ULL;

    for (int k0 = 0; k0 < DIM; k0 += KC) {
        #pragma unroll
        for (int i = 0; i < 4; i++) {
            int lin = tid + i * 256;
            int r = lin >> 3, kq = lin & 7;
            int row = rowBase + r;
            float4 v = make_float4(0.f, 0.f, 0.f, 0.f);
            if (row < N_ITEMS) v = *(const float4*)&d_ft[(size_t)row * DIM + k0 + kq * 4];
            As[kq*4+0][r] = v.x; As[kq*4+1][r] = v.y; As[kq*4+2][r] = v.z; As[kq*4+3][r] = v.w;
        }
        #pragma unroll
        for (int i = 0; i < 4; i++) {
            int lin = tid + i * 256;
            int kk = lin >> 5, nq = lin & 31;
            *(float4*)&Bs[kk][nq*4] = *(const float4*)&W_q[(k0 + kk) * DIM + nq * 4];
        }
        __syncthreads();
        #pragma unroll
        for (int kk = 0; kk < KC; kk++) {
            float4 a0 = *(const float4*)&As[kk][ty*8];
            float4 a1 = *(const float4*)&As[kk][ty*8+4];
            ulonglong2 b0 = *(const ulonglong2*)&Bs[kk][tx*8];
            ulonglong2 b1 = *(const ulonglong2*)&Bs[kk][tx*8+4];
            float av[8] = {a0.x,a0.y,a0.z,a0.w,a1.x,a1.y,a1.z,a1.w};
            unsigned long long bp[4] = {b0.x, b0.y, b1.x, b1.y};
            #pragma unroll
            for (int i = 0; i < 8; i++) {
                unsigned long long ad = pack2(av[i], av[i]);
                #pragma unroll
                for (int j = 0; j < 4; j++) fma2(acc[i][j], ad, bp[j]);
            }
        }
        __syncthreads();
    }
    #pragma unroll
    for (int i = 0; i < 8; i++) {
        int row = rowBase + ty * 8 + i;
        if (row < N_ITEMS) {
            float o[8];
            #pragma unroll
            for (int j = 0; j < 4; j++) { float2 p2 = unpack2(acc[i][j]); o[2*j] = p2.x; o[2*j+1] = p2.y; }
            *(float4*)&d_g[(size_t)row * DIM + tx*8]     = make_float4(o[0], o[1], o[2], o[3]);
            *(float4*)&d_g[(size_t)row * DIM + tx*8 + 4] = make_float4(o[4], o[5], o[6], o[7]);
        }
    }
}

// ---------------- K5: f = concat(h_t, ft[last]) @ W_r  (gathered-A GEMM) ----------------
__global__ __launch_bounds__(256) void gemm_f_kernel(
    const float* __restrict__ h_t, const float* __restrict__ W_r,
    const int* __restrict__ last_idx)
{
    __shared__ __align__(16) float As[KC][132];
    __shared__ __align__(16) float Bs[KC][128];
    int tid = threadIdx.x;
    int ty = tid >> 4, tx = tid & 15;
    int rowBase = blockIdx.x * 128;
    unsigned long long acc[8][4];
    #pragma unroll
    for (int i = 0; i < 8; i++)
        #pragma unroll
        for (int j = 0; j < 4; j++) acc[i][j] = 0ULL;

    for (int k0 = 0; k0 < 2 * DIM; k0 += KC) {
        #pragma unroll
        for (int i = 0; i < 4; i++) {
            int lin = tid + i * 256;
            int r = lin >> 3, kq = lin & 7;
            int row = rowBase + r;
            float4 v = make_float4(0.f, 0.f, 0.f, 0.f);
            if (row < N_TGT) {
                if (k0 < DIM) {
                    v = *(const float4*)&h_t[(size_t)row * DIM + k0 + kq * 4];
                } else {
                    int li = last_idx[row >> 2];
                    v = *(const float4*)&d_ft[(size_t)li * DIM + (k0 - DIM) + kq * 4];
                }
            }
            As[kq*4+0][r] = v.x; As[kq*4+1][r] = v.y; As[kq*4+2][r] = v.z; As[kq*4+3][r] = v.w;
        }
        #pragma unroll
        for (int i = 0; i < 4; i++) {
            int lin = tid + i * 256;
            int kk = lin >> 5, nq = lin & 31;
            *(float4*)&Bs[kk][nq*4] = *(const float4*)&W_r[(k0 + kk) * DIM + nq * 4];
        }
        __syncthreads();
        #pragma unroll
        for (int kk = 0; kk < KC; kk++) {
            float4 a0 = *(const float4*)&As[kk][ty*8];
            float4 a1 = *(const float4*)&As[kk][ty*8+4];
            ulonglong2 b0 = *(const ulonglong2*)&Bs[kk][tx*8];
            ulonglong2 b1 = *(const ulonglong2*)&Bs[kk][tx*8+4];
            float av[8] = {a0.x,a0.y,a0.z,a0.w,a1.x,a1.y,a1.z,a1.w};
            unsigned long long bp[4] = {b0.x, b0.y, b1.x, b1.y};
            #pragma unroll
            for (int i = 0; i < 8; i++) {
                unsigned long long ad = pack2(av[i], av[i]);
                #pragma unroll
                for (int j = 0; j < 4; j++) fma2(acc[i][j], ad, bp[j]);
            }
        }
        __syncthreads();
    }
    #pragma unroll
    for (int i = 0; i < 8; i++) {
        int row = rowBase + ty * 8 + i;
        if (row < N_TGT) {
            float o[8];
            #pragma unroll
            for (int j = 0; j < 4; j++) { float2 p2 = unpack2(acc[i][j]); o[2*j] = p2.x; o[2*j+1] = p2.y; }
            *(float4*)&d_f[(size_t)row * DIM + tx*8]     = make_float4(o[0], o[1], o[2], o[3]);
            *(float4*)&d_f[(size_t)row * DIM + tx*8 + 4] = make_float4(o[4], o[5], o[6], o[7]);
        }
    }
}

// ---------------- K6: mma.sync bf16-split GEMM + tanh + rowdot + scatter ----------------
// dynamic smem layout (bytes)
#define SM_AH   0
#define SM_AL   (SM_AH + BTILE)
#define SM_BH   (SM_AL + BTILE)
#define SM_BL   (SM_BH + BTILE)
#define SM_SRC  (SM_BL + BTILE)
#define SM_DST  (SM_SRC + 512)
#define SM_S    (SM_DST + 512)
#define SM_TOTAL (SM_S + 512)

__global__ __launch_bounds__(256, 1)
void edge2_mma_kernel(
    const float* __restrict__ h_p,
    const int* __restrict__ src2, const int* __restrict__ dst2,
    float* __restrict__ out)
{
    extern __shared__ __align__(16) char smem[];
    uint32_t sb = smem_to_u32(smem);
    int tid = threadIdx.x;
    int w = tid >> 5;          // warp 0..7 -> rows [16w, 16w+16)
    int lane = tid & 31;
    int eb = blockIdx.x * 128;

    int* ssrc = (int*)(smem + SM_SRC);
    int* sdst = (int*)(smem + SM_DST);
    float* s_s = (float*)(smem + SM_S);

    if (tid < 128) { ssrc[tid] = src2[eb + tid]; sdst[tid] = dst2[eb + tid]; }

    // copy prepped B hi/lo tiles (global -> smem), 2176 float4 each
    {
        const float4* gh = (const float4*)d_Bh2;
        const float4* gl = (const float4*)d_Bl2;
        float4* sh = (float4*)(smem + SM_BH);
        float4* sl = (float4*)(smem + SM_BL);
        for (int i = tid; i < BTILE / 16; i += 256) { sh[i] = gh[i]; sl[i] = gl[i]; }
    }

    // load A = h_p rows [eb, eb+128), split bf16 hi/lo into ROWB-padded smem
    {
        int row = tid >> 1;
        int ch = (tid & 1) * 64;
        const float4* pr = (const float4*)(h_p + (size_t)(eb + row) * DIM + ch);
        char* ah = smem + SM_AH + (uint32_t)row * ROWB;
        char* al = smem + SM_AL + (uint32_t)row * ROWB;
        #pragma unroll
        for (int i = 0; i < 16; i++) {
            float4 v = pr[i];
            int col = ch + i * 4;
            __nv_bfloat16 h0 = __float2bfloat16(v.x);
            __nv_bfloat16 h1 = __float2bfloat16(v.y);
            __nv_bfloat16 h2 = __float2bfloat16(v.z);
            __nv_bfloat16 h3 = __float2bfloat16(v.w);
            __nv_bfloat162 hp0; hp0.x = h0; hp0.y = h1;
            __nv_bfloat162 hp1; hp1.x = h2; hp1.y = h3;
            __nv_bfloat162 lp0 = __floats2bfloat162_rn(v.x - __bfloat162float(h0), v.y - __bfloat162float(h1));
            __nv_bfloat162 lp1 = __floats2bfloat162_rn(v.z - __bfloat162float(h2), v.w - __bfloat162float(h3));
            *(uint32_t*)(ah + col * 2)     = *(uint32_t*)&hp0;
            *(uint32_t*)(ah + col * 2 + 4) = *(uint32_t*)&hp1;
            *(uint32_t*)(al + col * 2)     = *(uint32_t*)&lp0;
            *(uint32_t*)(al + col * 2 + 4) = *(uint32_t*)&lp1;
        }
    }
    __syncthreads();

    // ---- mma mainloop ----
    float acc[16][4];
    #pragma unroll
    for (int t = 0; t < 16; t++)
        #pragma unroll
        for (int j = 0; j < 4; j++) acc[t][j] = 0.0f;

    int qi = lane & 7;            // row within 8x8 matrix
    int quad = lane >> 3;
    // A lane address offset: quad0:(m=i,k0) quad1:(m=i+8,k0) quad2:(m=i,k+8) quad3:(m=i+8,k+8)
    uint32_t a_lane = (uint32_t)(qi + ((quad & 1) ? 8 : 0)) * ROWB + ((quad >= 2) ? 16 : 0);
    uint32_t ah_base = sb + SM_AH + (uint32_t)w * 16 * ROWB + a_lane;
    uint32_t al_base = sb + SM_AL + (uint32_t)w * 16 * ROWB + a_lane;
    // B lane address offset: quad0:(n=i,k0) quad1:(n=i,k+8) quad2:(n=i+8,k0) quad3:(n=i+8,k+8)
    uint32_t b_lane = (uint32_t)(qi + ((quad >= 2) ? 8 : 0)) * ROWB + ((quad & 1) ? 16 : 0);
    uint32_t bh_base = sb + SM_BH + b_lane;
    uint32_t bl_base = sb + SM_BL + b_lane;

    #pragma unroll
    for (int k16 = 0; k16 < 8; k16++) {
        uint32_t koff = (uint32_t)k16 * 32;
        uint32_t ah0, ah1, ah2, ah3, al0, al1, al2, al3;
        ldsm_x4(ah0, ah1, ah2, ah3, ah_base + koff);
        ldsm_x4(al0, al1, al2, al3, al_base + koff);
        #pragma unroll
        for (int nt = 0; nt < 8; nt++) {
            uint32_t noff = (uint32_t)nt * (16 * ROWB) + koff;
            uint32_t bh0, bh1, bh2, bh3, bl0, bl1, bl2, bl3;
            ldsm_x4(bh0, bh1, bh2, bh3, bh_base + noff);
            ldsm_x4(bl0, bl1, bl2, bl3, bl_base + noff);
            int t0 = nt * 2, t1 = nt * 2 + 1;
            mma_bf16(acc[t0][0], acc[t0][1], acc[t0][2], acc[t0][3], ah0, ah1, ah2, ah3, bh0, bh1);
            mma_bf16(acc[t1][0], acc[t1][1], acc[t1][2], acc[t1][3], ah0, ah1, ah2, ah3, bh2, bh3);
            mma_bf16(acc[t0][0], acc[t0][1], acc[t0][2], acc[t0][3], ah0, ah1, ah2, ah3, bl0, bl1);
            mma_bf16(acc[t1][0], acc[t1][1], acc[t1][2], acc[t1][3], ah0, ah1, ah2, ah3, bl2, bl3);
            mma_bf16(acc[t0][0], acc[t0][1], acc[t0][2], acc[t0][3], al0, al1, al2, al3, bh0, bh1);
            mma_bf16(acc[t1][0], acc[t1][1], acc[t1][2], acc[t1][3], al0, al1, al2, al3, bh2, bh3);
        }
    }

    // ---- epilogue: e2 = tanh(acc + g[src]); s = sum(e2 * f[dst]) ----
    {
        int r0 = w * 16 + (lane >> 2);
        int r1 = r0 + 8;
        int src0 = ssrc[r0], dst0 = sdst[r0];
        int src1i = ssrc[r1], dst1i = sdst[r1];
        const float* g0p = d_g + (size_t)src0 * DIM;
        const float* f0p = d_f + (size_t)dst0 * DIM;
        const float* g1p = d_g + (size_t)src1i * DIM;
        const float* f1p = d_f + (size_t)dst1i * DIM;
        int c0 = (lane & 3) * 2;
        float s0 = 0.0f, s1 = 0.0f;
        #pragma unroll
        for (int t = 0; t < 16; t++) {
            int n = t * 8 + c0;
            float2 ga = *(const float2*)(g0p + n);
            float2 fa = *(const float2*)(f0p + n);
            float2 gb = *(const float2*)(g1p + n);
            float2 fb = *(const float2*)(f1p + n);
            s0 += tanh_fast(acc[t][0] + ga.x) * fa.x + tanh_fast(acc[t][1] + ga.y) * fa.y;
            s1 += tanh_fast(acc[t][2] + gb.x) * fb.x + tanh_fast(acc[t][3] + gb.y) * fb.y;
        }
        s0 += __shfl_xor_sync(0xffffffffu, s0, 1);
        s0 += __shfl_xor_sync(0xffffffffu, s0, 2);
        s1 += __shfl_xor_sync(0xffffffffu, s1, 1);
        s1 += __shfl_xor_sync(0xffffffffu, s1, 2);
        if ((lane & 3) == 0) { s_s[r0] = s0; s_s[r1] = s1; }
    }
    __syncthreads();

    // scatter: out[dst2[e]] += ft[src2[e]] * s[e]   (warp per row, coalesced red.v4)
    {
        for (int r = w * 16; r < w * 16 + 16; r++) {
            float sv = s_s[r];
            float4 v = ((const float4*)(d_ft + (size_t)ssrc[r] * DIM))[lane];
            v.x *= sv; v.y *= sv; v.z *= sv; v.w *= sv;
            red_add_v4(out + (size_t)sdst[r] * DIM + lane * 4, v);
        }
    }
}

// ---------------- launcher ----------------
extern "C" void kernel_launch(void* const* d_in, const int* in_sizes, int n_in,
                              void* d_out, int out_size) {
    const float* h_v  = (const float*)d_in[0];
    const float* h_d  = (const float*)d_in[1];
    const float* h_p  = (const float*)d_in[2];
    const float* h_t  = (const float*)d_in[3];
    const float* W_pi = (const float*)d_in[4];
    const float* W_M  = (const float*)d_in[5];
    const float* W_q  = (const float*)d_in[6];
    const float* W_r  = (const float*)d_in[7];
    const int* src1 = (const int*)d_in[8];
    const int* dst1 = (const int*)d_in[9];
    const int* src2 = (const int*)d_in[10];
    const int* dst2 = (const int*)d_in[11];
    const int* last_idx = (const int*)d_in[12];
    float* out = (float*)d_out;

    cudaFuncSetAttribute(edge2_mma_kernel, cudaFuncAttributeMaxDynamicSharedMemorySize, SM_TOTAL);

    init_kernel<<<2048, 256>>>(out);
    prep_wq_kernel<<<(DIM * DIM + 255) / 256, 256>>>(W_q);
    edge1_kernel<<<(E1N + 7) / 8, 256>>>(h_v, h_d, W_pi, W_M, src1, dst1);
    edge1_softmax_kernel<<<(E1N + 255) / 256, 256>>>(dst1);
    edge1_agg_kernel<<<E1N / 32, 256>>>(h_v, src1, dst1);
    gemm_g_kernel<<<(N_ITEMS + 127) / 128, 256>>>(W_q);
    gemm_f_kernel<<<(N_TGT + 127) / 128, 256>>>(h_t, W_r, last_idx);
    edge2_mma_kernel<<<E2N / 128, 256, SM_TOTAL>>>(h_p, src2, dst2, out);
}

// round 6
// speedup vs baseline: 1.2636x; 1.2636x over previous
#include <cuda_runtime.h>
#include <cuda_bf16.h>
#include <stdint.h>
#include <math.h>

#define N_ITEMS 100000
#define E1N 400000
#define E2N 400000
#define DIM 128
#define N_TGT 40000
#define KC 32

#define ROWB 272           // padded byte stride for 128 bf16 cols (conflict-free LDSM)
#define BTILE (128 * ROWB) // 34816 bytes per 128x128 bf16 tile

// ---------------- scratch (static device globals; no runtime allocation) ----------------
__device__ float d_ft[(size_t)N_ITEMS * DIM];   // aggregated item features
__device__ float d_g [(size_t)N_ITEMS * DIM];   // ft @ W_q[:128]
__device__ float d_f [(size_t)N_TGT  * DIM];    // concat(h_t, last) @ W_r
__device__ float d_e1[E1N];
__device__ float d_ex[E1N];
__device__ int   d_menc[N_ITEMS];
__device__ float d_z [N_ITEMS];
// prepped bf16 hi/lo images of W_q[128:256] transposed to [n][k], ROWB-padded rows
__device__ __align__(16) unsigned char d_Bh2[BTILE];
__device__ __align__(16) unsigned char d_Bl2[BTILE];

// ---------------- helpers ----------------
__device__ __forceinline__ int fenc(float f) {
    int i = __float_as_int(f);
    return (i >= 0) ? i : (i ^ 0x7FFFFFFF);
}
__device__ __forceinline__ float fdec(int i) {
    return __int_as_float((i >= 0) ? i : (i ^ 0x7FFFFFFF));
}
__device__ __forceinline__ unsigned long long pack2(float lo, float hi) {
    unsigned long long r;
    asm("mov.b64 %0, {%1, %2};" : "=l"(r) : "f"(lo), "f"(hi));
    return r;
}
__device__ __forceinline__ void fma2(unsigned long long &d, unsigned long long a, unsigned long long b) {
    asm("fma.rn.f32x2 %0, %1, %2, %0;" : "+l"(d) : "l"(a), "l"(b));
}
__device__ __forceinline__ float2 unpack2(unsigned long long v) {
    float lo, hi;
    asm("mov.b64 {%0, %1}, %2;" : "=f"(lo), "=f"(hi) : "l"(v));
    return make_float2(lo, hi);
}
__device__ __forceinline__ void red_add_v4(float* p, float4 v) {
    asm volatile("red.global.add.v4.f32 [%0], {%1, %2, %3, %4};"
                 :: "l"(p), "f"(v.x), "f"(v.y), "f"(v.z), "f"(v.w) : "memory");
}
__device__ __forceinline__ uint32_t smem_to_u32(const void* p) {
    uint32_t a;
    asm("{ .reg .u64 t; cvta.to.shared.u64 t, %1; cvt.u32.u64 %0, t; }" : "=r"(a) : "l"(p));
    return a;
}
__device__ __forceinline__ float tanh_fast(float x) {
    float r;
    asm("tanh.approx.f32 %0, %1;" : "=f"(r) : "f"(x));
    return r;
}
__device__ __forceinline__ void ldsm_x4(uint32_t &r0, uint32_t &r1, uint32_t &r2, uint32_t &r3, uint32_t addr) {
    asm volatile("ldmatrix.sync.aligned.m8n8.x4.shared.b16 {%0,%1,%2,%3}, [%4];"
                 : "=r"(r0), "=r"(r1), "=r"(r2), "=r"(r3) : "r"(addr));
}
__device__ __forceinline__ void mma_bf16(float &d0, float &d1, float &d2, float &d3,
                                         uint32_t a0, uint32_t a1, uint32_t a2, uint32_t a3,
                                         uint32_t b0, uint32_t b1) {
    asm volatile("mma.sync.aligned.m16n8k16.row.col.f32.bf16.bf16.f32 "
                 "{%0,%1,%2,%3}, {%4,%5,%6,%7}, {%8,%9}, {%0,%1,%2,%3};"
                 : "+f"(d0), "+f"(d1), "+f"(d2), "+f"(d3)
                 : "r"(a0), "r"(a1), "r"(a2), "r"(a3), "r"(b0), "r"(b1));
}
// split float2 -> bf16x2 hi + bf16x2 lo (residual)
__device__ __forceinline__ void split2(float2 v, uint32_t &hi, uint32_t &lo) {
    __nv_bfloat16 hx = __float2bfloat16(v.x);
    __nv_bfloat16 hy = __float2bfloat16(v.y);
    __nv_bfloat162 hp; hp.x = hx; hp.y = hy;
    __nv_bfloat162 lp = __floats2bfloat162_rn(v.x - __bfloat162float(hx),
                                              v.y - __bfloat162float(hy));
    hi = *(uint32_t*)&hp;
    lo = *(uint32_t*)&lp;
}

// ---------------- K0: init accumulators ----------------
__global__ void init_kernel(float* __restrict__ out) {
    int stride = gridDim.x * blockDim.x;
    int i0 = blockIdx.x * blockDim.x + threadIdx.x;
    for (int i = i0; i < N_ITEMS * DIM; i += stride) d_ft[i] = 0.0f;
    for (int i = i0; i < N_TGT * DIM;  i += stride) out[i]  = 0.0f;
    for (int i = i0; i < N_ITEMS;      i += stride) { d_z[i] = 0.0f; d_menc[i] = (int)0x80000000; }
}

// ---------------- prep: bf16 hi/lo of Wq_bot^T into [n][k] ROWB-padded layout ----------------
__global__ void prep_wq_kernel(const float* __restrict__ W_q) {
    int i = blockIdx.x * blockDim.x + threadIdx.x;
    if (i >= DIM * DIM) return;
    int n = i >> 7, k = i & 127;
    float w = W_q[(size_t)(DIM + k) * DIM + n];         // B^T[n][k] = W[128+k][n]
    __nv_bfloat16 hi = __float2bfloat16(w);
    __nv_bfloat16 lo = __float2bfloat16(w - __bfloat162float(hi));
    uint32_t off = (uint32_t)n * ROWB + k * 2;
    *(__nv_bfloat16*)(d_Bh2 + off) = hi;
    *(__nv_bfloat16*)(d_Bl2 + off) = lo;
}

// ---------------- K1: per-edge logit + segment max (2 edges per warp) ----------------
__global__ __launch_bounds__(256) void edge1_kernel(
    const float* __restrict__ h_v, const float* __restrict__ h_d,
    const float* __restrict__ W_pi, const float* __restrict__ W_M,
    const int* __restrict__ src1, const int* __restrict__ dst1)
{
    int warp = blockIdx.x * 8 + (threadIdx.x >> 5);
    int lane = threadIdx.x & 31;
    int e0 = warp * 2;                 // E1N divisible by 16 per block
    float4 p  = ((const float4*)W_pi)[lane];
    float4 ma = ((const float4*)W_M)[lane];
    float4 mb = ((const float4*)(W_M + DIM))[lane];
    int s0 = src1[e0], d0 = dst1[e0];
    int s1 = src1[e0 + 1], d1v = dst1[e0 + 1];
    float4 a0 = ((const float4*)(h_v + (size_t)s0 * DIM))[lane];
    float4 b0 = ((const float4*)(h_v + (size_t)d0 * DIM))[lane];
    float4 h0 = ((const float4*)(h_d + (size_t)e0 * DIM))[lane];
    float4 a1 = ((const float4*)(h_v + (size_t)s1 * DIM))[lane];
    float4 b1 = ((const float4*)(h_v + (size_t)d1v * DIM))[lane];
    float4 h1 = ((const float4*)(h_d + (size_t)(e0 + 1) * DIM))[lane];

    float4 uv0 = make_float4(a0.x*b0.x, a0.y*b0.y, a0.z*b0.z, a0.w*b0.w);
    float4 uv1 = make_float4(a1.x*b1.x, a1.y*b1.y, a1.z*b1.z, a1.w*b1.w);
    float e1a = uv0.x*h0.x*p.x + uv0.y*h0.y*p.y + uv0.z*h0.z*p.z + uv0.w*h0.w*p.w;
    float m1a = uv0.x*ma.x + uv0.y*ma.y + uv0.z*ma.z + uv0.w*ma.w
              + h0.x*mb.x + h0.y*mb.y + h0.z*mb.z + h0.w*mb.w;
    float e1b = uv1.x*h1.x*p.x + uv1.y*h1.y*p.y + uv1.z*h1.z*p.z + uv1.w*h1.w*p.w;
    float m1b = uv1.x*ma.x + uv1.y*ma.y + uv1.z*ma.z + uv1.w*ma.w
              + h1.x*mb.x + h1.y*mb.y + h1.z*mb.z + h1.w*mb.w;
    #pragma unroll
    for (int o = 16; o; o >>= 1) {
        e1a += __shfl_xor_sync(0xffffffffu, e1a, o);
        m1a += __shfl_xor_sync(0xffffffffu, m1a, o);
        e1b += __shfl_xor_sync(0xffffffffu, e1b, o);
        m1b += __shfl_xor_sync(0xffffffffu, m1b, o);
    }
    if (lane == 0) {
        float ev = e1a * (1.0f / (1.0f + expf(-m1a)));
        d_e1[e0] = ev;
        atomicMax(&d_menc[d0], fenc(ev));
        float ev2 = e1b * (1.0f / (1.0f + expf(-m1b)));
        d_e1[e0 + 1] = ev2;
        atomicMax(&d_menc[d1v], fenc(ev2));
    }
}

// ---------------- K2: exp + segment sum (thread per edge) ----------------
__global__ void edge1_softmax_kernel(const int* __restrict__ dst1) {
    int e = blockIdx.x * blockDim.x + threadIdx.x;
    if (e >= E1N) return;
    int d = dst1[e];
    float m = fdec(d_menc[d]);
    float v = expf(d_e1[e] - m);
    d_ex[e] = v;
    atomicAdd(&d_z[d], v);
}

// ---------------- K3: normalize + aggregate ft (4 edges per warp) ----------------
__global__ __launch_bounds__(256) void edge1_agg_kernel(
    const float* __restrict__ h_v,
    const int* __restrict__ src1, const int* __restrict__ dst1)
{
    int warp = blockIdx.x * 8 + (threadIdx.x >> 5);
    int lane = threadIdx.x & 31;
    int e0 = warp * 4;
    int s[4], d[4];
    #pragma unroll
    for (int i = 0; i < 4; i++) { s[i] = src1[e0 + i]; d[i] = dst1[e0 + i]; }
    float a[4];
    #pragma unroll
    for (int i = 0; i < 4; i++) a[i] = d_ex[e0 + i] / d_z[d[i]];
    float4 v[4];
    #pragma unroll
    for (int i = 0; i < 4; i++) v[i] = ((const float4*)(h_v + (size_t)s[i] * DIM))[lane];
    #pragma unroll
    for (int i = 0; i < 4; i++) {
        v[i].x *= a[i]; v[i].y *= a[i]; v[i].z *= a[i]; v[i].w *= a[i];
        red_add_v4(d_ft + (size_t)d[i] * DIM + lane * 4, v[i]);
    }
}

// ---------------- K4: g = ft @ W_q[:128]  (f32x2 register-tiled GEMM) ----------------
__global__ __launch_bounds__(256) void gemm_g_kernel(const float* __restrict__ W_q) {
    __shared__ __align__(16) float As[KC][132];
    __shared__ __align__(16) float Bs[KC][128];
    int tid = threadIdx.x;
    int ty = tid >> 4, tx = tid & 15;
    int rowBase = blockIdx.x * 128;
    unsigned long long acc[8][4];
    #pragma unroll
    for (int i = 0; i < 8; i++)
        #pragma unroll
        for (int j = 0; j < 4; j++) acc[i][j] = 0ULL;

    for (int k0 = 0; k0 < DIM; k0 += KC) {
        #pragma unroll
        for (int i = 0; i < 4; i++) {
            int lin = tid + i * 256;
            int r = lin >> 3, kq = lin & 7;
            int row = rowBase + r;
            float4 v = make_float4(0.f, 0.f, 0.f, 0.f);
            if (row < N_ITEMS) v = *(const float4*)&d_ft[(size_t)row * DIM + k0 + kq * 4];
            As[kq*4+0][r] = v.x; As[kq*4+1][r] = v.y; As[kq*4+2][r] = v.z; As[kq*4+3][r] = v.w;
        }
        #pragma unroll
        for (int i = 0; i < 4; i++) {
            int lin = tid + i * 256;
            int kk = lin >> 5, nq = lin & 31;
            *(float4*)&Bs[kk][nq*4] = *(const float4*)&W_q[(k0 + kk) * DIM + nq * 4];
        }
        __syncthreads();
        #pragma unroll
        for (int kk = 0; kk < KC; kk++) {
            float4 a0 = *(const float4*)&As[kk][ty*8];
            float4 a1 = *(const float4*)&As[kk][ty*8+4];
            ulonglong2 b0 = *(const ulonglong2*)&Bs[kk][tx*8];
            ulonglong2 b1 = *(const ulonglong2*)&Bs[kk][tx*8+4];
            float av[8] = {a0.x,a0.y,a0.z,a0.w,a1.x,a1.y,a1.z,a1.w};
            unsigned long long bp[4] = {b0.x, b0.y, b1.x, b1.y};
            #pragma unroll
            for (int i = 0; i < 8; i++) {
                unsigned long long ad = pack2(av[i], av[i]);
                #pragma unroll
                for (int j = 0; j < 4; j++) fma2(acc[i][j], ad, bp[j]);
            }
        }
        __syncthreads();
    }
    #pragma unroll
    for (int i = 0; i < 8; i++) {
        int row = rowBase + ty * 8 + i;
        if (row < N_ITEMS) {
            float o[8];
            #pragma unroll
            for (int j = 0; j < 4; j++) { float2 p2 = unpack2(acc[i][j]); o[2*j] = p2.x; o[2*j+1] = p2.y; }
            *(float4*)&d_g[(size_t)row * DIM + tx*8]     = make_float4(o[0], o[1], o[2], o[3]);
            *(float4*)&d_g[(size_t)row * DIM + tx*8 + 4] = make_float4(o[4], o[5], o[6], o[7]);
        }
    }
}

// ---------------- K5: f = concat(h_t, ft[last]) @ W_r  (gathered-A GEMM) ----------------
__global__ __launch_bounds__(256) void gemm_f_kernel(
    const float* __restrict__ h_t, const float* __restrict__ W_r,
    const int* __restrict__ last_idx)
{
    __shared__ __align__(16) float As[KC][132];
    __shared__ __align__(16) float Bs[KC][128];
    int tid = threadIdx.x;
    int ty = tid >> 4, tx = tid & 15;
    int rowBase = blockIdx.x * 128;
    unsigned long long acc[8][4];
    #pragma unroll
    for (int i = 0; i < 8; i++)
        #pragma unroll
        for (int j = 0; j < 4; j++) acc[i][j] = 0ULL;

    for (int k0 = 0; k0 < 2 * DIM; k0 += KC) {
        #pragma unroll
        for (int i = 0; i < 4; i++) {
            int lin = tid + i * 256;
            int r = lin >> 3, kq = lin & 7;
            int row = rowBase + r;
            float4 v = make_float4(0.f, 0.f, 0.f, 0.f);
            if (row < N_TGT) {
                if (k0 < DIM) {
                    v = *(const float4*)&h_t[(size_t)row * DIM + k0 + kq * 4];
                } else {
                    int li = last_idx[row >> 2];
                    v = *(const float4*)&d_ft[(size_t)li * DIM + (k0 - DIM) + kq * 4];
                }
            }
            As[kq*4+0][r] = v.x; As[kq*4+1][r] = v.y; As[kq*4+2][r] = v.z; As[kq*4+3][r] = v.w;
        }
        #pragma unroll
        for (int i = 0; i < 4; i++) {
            int lin = tid + i * 256;
            int kk = lin >> 5, nq = lin & 31;
            *(float4*)&Bs[kk][nq*4] = *(const float4*)&W_r[(k0 + kk) * DIM + nq * 4];
        }
        __syncthreads();
        #pragma unroll
        for (int kk = 0; kk < KC; kk++) {
            float4 a0 = *(const float4*)&As[kk][ty*8];
            float4 a1 = *(const float4*)&As[kk][ty*8+4];
            ulonglong2 b0 = *(const ulonglong2*)&Bs[kk][tx*8];
            ulonglong2 b1 = *(const ulonglong2*)&Bs[kk][tx*8+4];
            float av[8] = {a0.x,a0.y,a0.z,a0.w,a1.x,a1.y,a1.z,a1.w};
            unsigned long long bp[4] = {b0.x, b0.y, b1.x, b1.y};
            #pragma unroll
            for (int i = 0; i < 8; i++) {
                unsigned long long ad = pack2(av[i], av[i]);
                #pragma unroll
                for (int j = 0; j < 4; j++) fma2(acc[i][j], ad, bp[j]);
            }
        }
        __syncthreads();
    }
    #pragma unroll
    for (int i = 0; i < 8; i++) {
        int row = rowBase + ty * 8 + i;
        if (row < N_TGT) {
            float o[8];
            #pragma unroll
            for (int j = 0; j < 4; j++) { float2 p2 = unpack2(acc[i][j]); o[2*j] = p2.x; o[2*j+1] = p2.y; }
            *(float4*)&d_f[(size_t)row * DIM + tx*8]     = make_float4(o[0], o[1], o[2], o[3]);
            *(float4*)&d_f[(size_t)row * DIM + tx*8 + 4] = make_float4(o[4], o[5], o[6], o[7]);
        }
    }
}

// ---------------- K6: mma.sync, A from global regs, B in smem; occupancy 2 ----------------
// dynamic smem layout (bytes)
#define SM_BH   0
#define SM_BL   BTILE
#define SM_SRC  (2 * BTILE)
#define SM_DST  (SM_SRC + 512)
#define SM_S    (SM_DST + 512)
#define SM_TOTAL (SM_S + 512)

__global__ __launch_bounds__(256, 2)
void edge2_mma_kernel(
    const float* __restrict__ h_p,
    const int* __restrict__ src2, const int* __restrict__ dst2,
    float* __restrict__ out)
{
    extern __shared__ __align__(16) char smem[];
    uint32_t sb = smem_to_u32(smem);
    int tid = threadIdx.x;
    int w = tid >> 5;          // warp 0..7 -> rows [16w, 16w+16)
    int lane = tid & 31;
    int eb = blockIdx.x * 128;

    int* ssrc = (int*)(smem + SM_SRC);
    int* sdst = (int*)(smem + SM_DST);
    float* s_s = (float*)(smem + SM_S);

    if (tid < 128) { ssrc[tid] = src2[eb + tid]; sdst[tid] = dst2[eb + tid]; }

    // copy prepped B hi/lo tiles (global -> smem), read from L2 (broadcast across blocks)
    {
        const float4* gh = (const float4*)d_Bh2;
        const float4* gl = (const float4*)d_Bl2;
        float4* sh = (float4*)(smem + SM_BH);
        float4* sl = (float4*)(smem + SM_BL);
        for (int i = tid; i < BTILE / 16; i += 256) { sh[i] = gh[i]; sl[i] = gl[i]; }
    }
    __syncthreads();

    // ---- mma mainloop: A fragments loaded directly from global fp32 + split in regs ----
    float acc[16][4];
    #pragma unroll
    for (int t = 0; t < 16; t++)
        #pragma unroll
        for (int j = 0; j < 4; j++) acc[t][j] = 0.0f;

    int qi = lane & 7;
    int quad = lane >> 3;
    // B lane address offset (validated in R4): quad0:(n=i,k0) quad1:(n=i,k+8) quad2:(n=i+8,k0) quad3:(n=i+8,k+8)
    uint32_t b_lane = (uint32_t)(qi + ((quad >= 2) ? 8 : 0)) * ROWB + ((quad & 1) ? 16 : 0);
    uint32_t bh_base = sb + SM_BH + b_lane;
    uint32_t bl_base = sb + SM_BL + b_lane;

    // A row pointers for this lane (m16n8k16 row-major frag: rows lane>>2 and +8)
    const float* pa = h_p + (size_t)(eb + w * 16 + (lane >> 2)) * DIM;
    const float* pb = pa + 8 * DIM;
    int c0 = (lane & 3) * 2;

    #pragma unroll
    for (int k16 = 0; k16 < 8; k16++) {
        int kbase = k16 * 16 + c0;
        float2 v00 = *(const float2*)(pa + kbase);        // a0: (row, k)
        float2 v10 = *(const float2*)(pb + kbase);        // a1: (row+8, k)
        float2 v01 = *(const float2*)(pa + kbase + 8);    // a2: (row, k+8)
        float2 v11 = *(const float2*)(pb + kbase + 8);    // a3: (row+8, k+8)
        uint32_t ah0, ah1, ah2, ah3, al0, al1, al2, al3;
        split2(v00, ah0, al0);
        split2(v10, ah1, al1);
        split2(v01, ah2, al2);
        split2(v11, ah3, al3);

        uint32_t koff = (uint32_t)k16 * 32;
        #pragma unroll
        for (int nt = 0; nt < 8; nt++) {
            uint32_t noff = (uint32_t)nt * (16 * ROWB) + koff;
            uint32_t bh0, bh1, bh2, bh3, bl0, bl1, bl2, bl3;
            ldsm_x4(bh0, bh1, bh2, bh3, bh_base + noff);
            ldsm_x4(bl0, bl1, bl2, bl3, bl_base + noff);
            int t0 = nt * 2, t1 = nt * 2 + 1;
            mma_bf16(acc[t0][0], acc[t0][1], acc[t0][2], acc[t0][3], ah0, ah1, ah2, ah3, bh0, bh1);
            mma_bf16(acc[t1][0], acc[t1][1], acc[t1][2], acc[t1][3], ah0, ah1, ah2, ah3, bh2, bh3);
            mma_bf16(acc[t0][0], acc[t0][1], acc[t0][2], acc[t0][3], ah0, ah1, ah2, ah3, bl0, bl1);
            mma_bf16(acc[t1][0], acc[t1][1], acc[t1][2], acc[t1][3], ah0, ah1, ah2, ah3, bl2, bl3);
            mma_bf16(acc[t0][0], acc[t0][1], acc[t0][2], acc[t0][3], al0, al1, al2, al3, bh0, bh1);
            mma_bf16(acc[t1][0], acc[t1][1], acc[t1][2], acc[t1][3], al0, al1, al2, al3, bh2, bh3);
        }
    }

    // ---- epilogue: e2 = tanh(acc + g[src]); s = sum(e2 * f[dst]) ----
    {
        int r0 = w * 16 + (lane >> 2);
        int r1 = r0 + 8;
        int src0 = ssrc[r0], dst0 = sdst[r0];
        int src1i = ssrc[r1], dst1i = sdst[r1];
        const float* g0p = d_g + (size_t)src0 * DIM;
        const float* f0p = d_f + (size_t)dst0 * DIM;
        const float* g1p = d_g + (size_t)src1i * DIM;
        const float* f1p = d_f + (size_t)dst1i * DIM;
        float s0 = 0.0f, s1 = 0.0f;
        #pragma unroll
        for (int t = 0; t < 16; t++) {
            int n = t * 8 + c0;
            float2 ga = *(const float2*)(g0p + n);
            float2 fa = *(const float2*)(f0p + n);
            float2 gb = *(const float2*)(g1p + n);
            float2 fb = *(const float2*)(f1p + n);
            s0 += tanh_fast(acc[t][0] + ga.x) * fa.x + tanh_fast(acc[t][1] + ga.y) * fa.y;
            s1 += tanh_fast(acc[t][2] + gb.x) * fb.x + tanh_fast(acc[t][3] + gb.y) * fb.y;
        }
        s0 += __shfl_xor_sync(0xffffffffu, s0, 1);
        s0 += __shfl_xor_sync(0xffffffffu, s0, 2);
        s1 += __shfl_xor_sync(0xffffffffu, s1, 1);
        s1 += __shfl_xor_sync(0xffffffffu, s1, 2);
        if ((lane & 3) == 0) { s_s[r0] = s0; s_s[r1] = s1; }
    }
    __syncthreads();

    // scatter: out[dst2[e]] += ft[src2[e]] * s[e]   (warp per row, coalesced red.v4)
    {
        #pragma unroll 4
        for (int r = w * 16; r < w * 16 + 16; r++) {
            float sv = s_s[r];
            float4 v = ((const float4*)(d_ft + (size_t)ssrc[r] * DIM))[lane];
            v.x *= sv; v.y *= sv; v.z *= sv; v.w *= sv;
            red_add_v4(out + (size_t)sdst[r] * DIM + lane * 4, v);
        }
    }
}

// ---------------- launcher ----------------
extern "C" void kernel_launch(void* const* d_in, const int* in_sizes, int n_in,
                              void* d_out, int out_size) {
    const float* h_v  = (const float*)d_in[0];
    const float* h_d  = (const float*)d_in[1];
    const float* h_p  = (const float*)d_in[2];
    const float* h_t  = (const float*)d_in[3];
    const float* W_pi = (const float*)d_in[4];
    const float* W_M  = (const float*)d_in[5];
    const float* W_q  = (const float*)d_in[6];
    const float* W_r  = (const float*)d_in[7];
    const int* src1 = (const int*)d_in[8];
    const int* dst1 = (const int*)d_in[9];
    const int* src2 = (const int*)d_in[10];
    const int* dst2 = (const int*)d_in[11];
    const int* last_idx = (const int*)d_in[12];
    float* out = (float*)d_out;

    cudaFuncSetAttribute(edge2_mma_kernel, cudaFuncAttributeMaxDynamicSharedMemorySize, SM_TOTAL);

    init_kernel<<<2048, 256>>>(out);                        // launch 0
    edge1_kernel<<<E1N / 16, 256>>>(h_v, h_d, W_pi, W_M, src1, dst1);   // 1
    edge1_softmax_kernel<<<(E1N + 255) / 256, 256>>>(dst1); // 2
    edge1_agg_kernel<<<E1N / 32, 256>>>(h_v, src1, dst1);   // 3  <- profiled launch
    prep_wq_kernel<<<(DIM * DIM + 255) / 256, 256>>>(W_q);  // 4
    gemm_g_kernel<<<(N_ITEMS + 127) / 128, 256>>>(W_q);     // 5
    gemm_f_kernel<<<(N_TGT + 127) / 128, 256>>>(h_t, W_r, last_idx);    // 6
    edge2_mma_kernel<<<E2N / 128, 256, SM_TOTAL>>>(h_p, src2, dst2, out); // 7
}

// round 7
// speedup vs baseline: 1.5204x; 1.2032x over previous
#include <cuda_runtime.h>
#include <cuda_bf16.h>
#include <stdint.h>
#include <math.h>

#define N_ITEMS 100000
#define E1N 400000
#define E2N 400000
#define DIM 128
#define N_TGT 40000

#define ROWB 272           // padded byte stride for 128 bf16 cols (conflict-free LDSM)
#define BTILE (128 * ROWB) // 34816 bytes per 128x128 bf16 tile

// ---------------- scratch (static device globals; no runtime allocation) ----------------
__device__ float d_ft[(size_t)N_ITEMS * DIM];   // aggregated item features
__device__ float d_g [(size_t)N_ITEMS * DIM];   // ft @ W_q[:128]
__device__ float d_f [(size_t)N_TGT  * DIM];    // concat(h_t, last) @ W_r
__device__ float d_e1[E1N];
__device__ float d_ex[E1N];
__device__ int   d_menc[N_ITEMS];
__device__ float d_z [N_ITEMS];
// prepped bf16 hi/lo weight tiles, [n][k] ROWB-padded:
__device__ __align__(16) unsigned char d_BhT[BTILE];  // W_q[0:128]^T   (gemm_g)
__device__ __align__(16) unsigned char d_BlT[BTILE];
__device__ __align__(16) unsigned char d_Bh2[BTILE];  // W_q[128:256]^T (edge2)
__device__ __align__(16) unsigned char d_Bl2[BTILE];
__device__ __align__(16) unsigned char d_BhR0[BTILE]; // W_r[0:128]^T   (gemm_f)
__device__ __align__(16) unsigned char d_BlR0[BTILE];
__device__ __align__(16) unsigned char d_BhR1[BTILE]; // W_r[128:256]^T (gemm_f)
__device__ __align__(16) unsigned char d_BlR1[BTILE];

// ---------------- helpers ----------------
__device__ __forceinline__ int fenc(float f) {
    int i = __float_as_int(f);
    return (i >= 0) ? i : (i ^ 0x7FFFFFFF);
}
__device__ __forceinline__ float fdec(int i) {
    return __int_as_float((i >= 0) ? i : (i ^ 0x7FFFFFFF));
}
__device__ __forceinline__ void red_add_v4(float* p, float4 v) {
    asm volatile("red.global.add.v4.f32 [%0], {%1, %2, %3, %4};"
                 :: "l"(p), "f"(v.x), "f"(v.y), "f"(v.z), "f"(v.w) : "memory");
}
__device__ __forceinline__ uint32_t smem_to_u32(const void* p) {
    uint32_t a;
    asm("{ .reg .u64 t; cvta.to.shared.u64 t, %1; cvt.u32.u64 %0, t; }" : "=r"(a) : "l"(p));
    return a;
}
__device__ __forceinline__ float tanh_fast(float x) {
    float r;
    asm("tanh.approx.f32 %0, %1;" : "=f"(r) : "f"(x));
    return r;
}
__device__ __forceinline__ void ldsm_x4(uint32_t &r0, uint32_t &r1, uint32_t &r2, uint32_t &r3, uint32_t addr) {
    asm volatile("ldmatrix.sync.aligned.m8n8.x4.shared.b16 {%0,%1,%2,%3}, [%4];"
                 : "=r"(r0), "=r"(r1), "=r"(r2), "=r"(r3) : "r"(addr));
}
__device__ __forceinline__ void mma_bf16(float &d0, float &d1, float &d2, float &d3,
                                         uint32_t a0, uint32_t a1, uint32_t a2, uint32_t a3,
                                         uint32_t b0, uint32_t b1) {
    asm volatile("mma.sync.aligned.m16n8k16.row.col.f32.bf16.bf16.f32 "
                 "{%0,%1,%2,%3}, {%4,%5,%6,%7}, {%8,%9}, {%0,%1,%2,%3};"
                 : "+f"(d0), "+f"(d1), "+f"(d2), "+f"(d3)
                 : "r"(a0), "r"(a1), "r"(a2), "r"(a3), "r"(b0), "r"(b1));
}
// split float2 -> bf16x2 hi + bf16x2 lo (residual)
__device__ __forceinline__ void split2(float2 v, uint32_t &hi, uint32_t &lo) {
    __nv_bfloat16 hx = __float2bfloat16(v.x);
    __nv_bfloat16 hy = __float2bfloat16(v.y);
    __nv_bfloat162 hp; hp.x = hx; hp.y = hy;
    __nv_bfloat162 lp = __floats2bfloat162_rn(v.x - __bfloat162float(hx),
                                              v.y - __bfloat162float(hy));
    hi = *(uint32_t*)&hp;
    lo = *(uint32_t*)&lp;
}

// 3-term split-mma inner step over one k16 x 128-N strip (shared by all mma kernels)
#define MMA_STRIP(koff)                                                                        \
    _Pragma("unroll")                                                                          \
    for (int nt = 0; nt < 8; nt++) {                                                           \
        uint32_t noff = (uint32_t)nt * (16 * ROWB) + (koff);                                   \
        uint32_t bh0, bh1, bh2, bh3, bl0, bl1, bl2, bl3;                                       \
        ldsm_x4(bh0, bh1, bh2, bh3, bh_base + noff);                                           \
        ldsm_x4(bl0, bl1, bl2, bl3, bl_base + noff);                                           \
        int t0 = nt * 2, t1 = nt * 2 + 1;                                                      \
        mma_bf16(acc[t0][0], acc[t0][1], acc[t0][2], acc[t0][3], ah0, ah1, ah2, ah3, bh0, bh1);\
        mma_bf16(acc[t1][0], acc[t1][1], acc[t1][2], acc[t1][3], ah0, ah1, ah2, ah3, bh2, bh3);\
        mma_bf16(acc[t0][0], acc[t0][1], acc[t0][2], acc[t0][3], ah0, ah1, ah2, ah3, bl0, bl1);\
        mma_bf16(acc[t1][0], acc[t1][1], acc[t1][2], acc[t1][3], ah0, ah1, ah2, ah3, bl2, bl3);\
        mma_bf16(acc[t0][0], acc[t0][1], acc[t0][2], acc[t0][3], al0, al1, al2, al3, bh0, bh1);\
        mma_bf16(acc[t1][0], acc[t1][1], acc[t1][2], acc[t1][3], al0, al1, al2, al3, bh2, bh3);\
    }

#define LOAD_A_FRAGS(pa, pb, kbase)                                                            \
    uint32_t ah0, ah1, ah2, ah3, al0, al1, al2, al3;                                           \
    {                                                                                          \
        float2 v00 = *(const float2*)((pa) + (kbase));                                         \
        float2 v10 = *(const float2*)((pb) + (kbase));                                         \
        float2 v01 = *(const float2*)((pa) + (kbase) + 8);                                     \
        float2 v11 = *(const float2*)((pb) + (kbase) + 8);                                     \
        split2(v00, ah0, al0);                                                                 \
        split2(v10, ah1, al1);                                                                 \
        split2(v01, ah2, al2);                                                                 \
        split2(v11, ah3, al3);                                                                 \
    }

// ---------------- K0: init accumulators ----------------
__global__ void init_kernel(float* __restrict__ out) {
    int stride = gridDim.x * blockDim.x;
    int i0 = blockIdx.x * blockDim.x + threadIdx.x;
    for (int i = i0; i < N_ITEMS * DIM; i += stride) d_ft[i] = 0.0f;
    for (int i = i0; i < N_TGT * DIM;  i += stride) out[i]  = 0.0f;
    for (int i = i0; i < N_ITEMS;      i += stride) { d_z[i] = 0.0f; d_menc[i] = (int)0x80000000; }
}

// ---------------- prep: bf16 hi/lo transposed tiles of W_q (both halves) ----------------
__global__ void prep_wq_kernel(const float* __restrict__ W_q) {
    int i = blockIdx.x * blockDim.x + threadIdx.x;
    if (i >= 2 * DIM * DIM) return;
    int half = i >> 14;
    int j = i & 16383;
    int n = j >> 7, k = j & 127;
    float w = W_q[(size_t)(half * DIM + k) * DIM + n];
    __nv_bfloat16 hi = __float2bfloat16(w);
    __nv_bfloat16 lo = __float2bfloat16(w - __bfloat162float(hi));
    uint32_t off = (uint32_t)n * ROWB + k * 2;
    unsigned char* bh = half ? d_Bh2 : d_BhT;
    unsigned char* bl = half ? d_Bl2 : d_BlT;
    *(__nv_bfloat16*)(bh + off) = hi;
    *(__nv_bfloat16*)(bl + off) = lo;
}

// ---------------- prep: bf16 hi/lo transposed tiles of W_r (both halves) ----------------
__global__ void prep_wr_kernel(const float* __restrict__ W_r) {
    int i = blockIdx.x * blockDim.x + threadIdx.x;
    if (i >= 2 * DIM * DIM) return;
    int half = i >> 14;
    int j = i & 16383;
    int n = j >> 7, k = j & 127;
    float w = W_r[(size_t)(half * DIM + k) * DIM + n];
    __nv_bfloat16 hi = __float2bfloat16(w);
    __nv_bfloat16 lo = __float2bfloat16(w - __bfloat162float(hi));
    uint32_t off = (uint32_t)n * ROWB + k * 2;
    unsigned char* bh = half ? d_BhR1 : d_BhR0;
    unsigned char* bl = half ? d_BlR1 : d_BlR0;
    *(__nv_bfloat16*)(bh + off) = hi;
    *(__nv_bfloat16*)(bl + off) = lo;
}

// ---------------- K1: per-edge logit + segment max (4 edges per warp) ----------------
__global__ __launch_bounds__(256) void edge1_kernel(
    const float* __restrict__ h_v, const float* __restrict__ h_d,
    const float* __restrict__ W_pi, const float* __restrict__ W_M,
    const int* __restrict__ src1, const int* __restrict__ dst1)
{
    int warp = blockIdx.x * 8 + (threadIdx.x >> 5);
    int lane = threadIdx.x & 31;
    int e0 = warp * 4;
    float4 p  = ((const float4*)W_pi)[lane];
    float4 ma = ((const float4*)W_M)[lane];
    float4 mb = ((const float4*)(W_M + DIM))[lane];
    int s[4], d[4];
    #pragma unroll
    for (int i = 0; i < 4; i++) { s[i] = src1[e0 + i]; d[i] = dst1[e0 + i]; }
    float4 a[4], b[4], hh[4];
    #pragma unroll
    for (int i = 0; i < 4; i++) {
        a[i]  = ((const float4*)(h_v + (size_t)s[i] * DIM))[lane];
        b[i]  = ((const float4*)(h_v + (size_t)d[i] * DIM))[lane];
        hh[i] = ((const float4*)(h_d + (size_t)(e0 + i) * DIM))[lane];
    }
    float ev[4], mv[4];
    #pragma unroll
    for (int i = 0; i < 4; i++) {
        float4 uv = make_float4(a[i].x*b[i].x, a[i].y*b[i].y, a[i].z*b[i].z, a[i].w*b[i].w);
        ev[i] = uv.x*hh[i].x*p.x + uv.y*hh[i].y*p.y + uv.z*hh[i].z*p.z + uv.w*hh[i].w*p.w;
        mv[i] = uv.x*ma.x + uv.y*ma.y + uv.z*ma.z + uv.w*ma.w
              + hh[i].x*mb.x + hh[i].y*mb.y + hh[i].z*mb.z + hh[i].w*mb.w;
    }
    #pragma unroll
    for (int o = 16; o; o >>= 1) {
        #pragma unroll
        for (int i = 0; i < 4; i++) {
            ev[i] += __shfl_xor_sync(0xffffffffu, ev[i], o);
            mv[i] += __shfl_xor_sync(0xffffffffu, mv[i], o);
        }
    }
    if (lane == 0) {
        #pragma unroll
        for (int i = 0; i < 4; i++) {
            float e = ev[i] * (1.0f / (1.0f + expf(-mv[i])));
            d_e1[e0 + i] = e;
            atomicMax(&d_menc[d[i]], fenc(e));
        }
    }
}

// ---------------- K2: exp + segment sum (thread per edge) ----------------
__global__ void edge1_softmax_kernel(const int* __restrict__ dst1) {
    int e = blockIdx.x * blockDim.x + threadIdx.x;
    if (e >= E1N) return;
    int d = dst1[e];
    float m = fdec(d_menc[d]);
    float v = expf(d_e1[e] - m);
    d_ex[e] = v;
    atomicAdd(&d_z[d], v);
}

// ---------------- K3: normalize + aggregate ft (4 edges per warp) ----------------
__global__ __launch_bounds__(256) void edge1_agg_kernel(
    const float* __restrict__ h_v,
    const int* __restrict__ src1, const int* __restrict__ dst1)
{
    int warp = blockIdx.x * 8 + (threadIdx.x >> 5);
    int lane = threadIdx.x & 31;
    int e0 = warp * 4;
    int s[4], d[4];
    #pragma unroll
    for (int i = 0; i < 4; i++) { s[i] = src1[e0 + i]; d[i] = dst1[e0 + i]; }
    float a[4];
    #pragma unroll
    for (int i = 0; i < 4; i++) a[i] = d_ex[e0 + i] / d_z[d[i]];
    float4 v[4];
    #pragma unroll
    for (int i = 0; i < 4; i++) v[i] = ((const float4*)(h_v + (size_t)s[i] * DIM))[lane];
    #pragma unroll
    for (int i = 0; i < 4; i++) {
        v[i].x *= a[i]; v[i].y *= a[i]; v[i].z *= a[i]; v[i].w *= a[i];
        red_add_v4(d_ft + (size_t)d[i] * DIM + lane * 4, v[i]);
    }
}

// ---------------- K4: g = ft @ W_q[:128]  (mma.sync bf16-split) ----------------
#define SMG_TOTAL (2 * BTILE)
__global__ __launch_bounds__(256, 2) void gemm_g_mma() {
    extern __shared__ __align__(16) char smem[];
    uint32_t sb = smem_to_u32(smem);
    int tid = threadIdx.x;
    int w = tid >> 5;
    int lane = tid & 31;

    {
        const float4* gh = (const float4*)d_BhT;
        const float4* gl = (const float4*)d_BlT;
        float4* sh = (float4*)smem;
        float4* sl = (float4*)(smem + BTILE);
        for (int i = tid; i < BTILE / 16; i += 256) { sh[i] = gh[i]; sl[i] = gl[i]; }
    }
    __syncthreads();

    float acc[16][4];
    #pragma unroll
    for (int t = 0; t < 16; t++)
        #pragma unroll
        for (int j = 0; j < 4; j++) acc[t][j] = 0.0f;

    int qi = lane & 7;
    int quad = lane >> 3;
    uint32_t b_lane = (uint32_t)(qi + ((quad >= 2) ? 8 : 0)) * ROWB + ((quad & 1) ? 16 : 0);
    uint32_t bh_base = sb + b_lane;
    uint32_t bl_base = sb + BTILE + b_lane;

    int row0 = blockIdx.x * 128 + w * 16 + (lane >> 2);
    int row1 = row0 + 8;
    int r0c = (row0 < N_ITEMS) ? row0 : (N_ITEMS - 1);
    int r1c = (row1 < N_ITEMS) ? row1 : (N_ITEMS - 1);
    const float* pa = d_ft + (size_t)r0c * DIM;
    const float* pb = d_ft + (size_t)r1c * DIM;
    int c0 = (lane & 3) * 2;

    #pragma unroll
    for (int k16 = 0; k16 < 8; k16++) {
        LOAD_A_FRAGS(pa, pb, k16 * 16 + c0);
        uint32_t koff = (uint32_t)k16 * 32;
        MMA_STRIP(koff);
    }

    #pragma unroll
    for (int t = 0; t < 16; t++) {
        int n = t * 8 + c0;
        if (row0 < N_ITEMS) *(float2*)&d_g[(size_t)row0 * DIM + n] = make_float2(acc[t][0], acc[t][1]);
        if (row1 < N_ITEMS) *(float2*)&d_g[(size_t)row1 * DIM + n] = make_float2(acc[t][2], acc[t][3]);
    }
}

// ---------------- K5: f = concat(h_t, ft[last]) @ W_r  (mma.sync, 2-phase K) ----------------
__global__ __launch_bounds__(256, 2) void gemm_f_mma(
    const float* __restrict__ h_t, const int* __restrict__ last_idx)
{
    extern __shared__ __align__(16) char smem[];
    uint32_t sb = smem_to_u32(smem);
    int tid = threadIdx.x;
    int w = tid >> 5;
    int lane = tid & 31;

    float acc[16][4];
    #pragma unroll
    for (int t = 0; t < 16; t++)
        #pragma unroll
        for (int j = 0; j < 4; j++) acc[t][j] = 0.0f;

    int qi = lane & 7;
    int quad = lane >> 3;
    uint32_t b_lane = (uint32_t)(qi + ((quad >= 2) ? 8 : 0)) * ROWB + ((quad & 1) ? 16 : 0);
    uint32_t bh_base = sb + b_lane;
    uint32_t bl_base = sb + BTILE + b_lane;

    int row0 = blockIdx.x * 128 + w * 16 + (lane >> 2);
    int row1 = row0 + 8;
    int r0c = (row0 < N_TGT) ? row0 : (N_TGT - 1);
    int r1c = (row1 < N_TGT) ? row1 : (N_TGT - 1);
    int c0 = (lane & 3) * 2;

    // phase 0: B = W_r[0:128]^T, A = h_t
    {
        const float4* gh = (const float4*)d_BhR0;
        const float4* gl = (const float4*)d_BlR0;
        float4* sh = (float4*)smem;
        float4* sl = (float4*)(smem + BTILE);
        for (int i = tid; i < BTILE / 16; i += 256) { sh[i] = gh[i]; sl[i] = gl[i]; }
    }
    __syncthreads();
    {
        const float* pa = h_t + (size_t)r0c * DIM;
        const float* pb = h_t + (size_t)r1c * DIM;
        #pragma unroll
        for (int k16 = 0; k16 < 8; k16++) {
            LOAD_A_FRAGS(pa, pb, k16 * 16 + c0);
            uint32_t koff = (uint32_t)k16 * 32;
            MMA_STRIP(koff);
        }
    }
    __syncthreads();

    // phase 1: B = W_r[128:256]^T, A = ft[last_idx[row/4]]
    {
        const float4* gh = (const float4*)d_BhR1;
        const float4* gl = (const float4*)d_BlR1;
        float4* sh = (float4*)smem;
        float4* sl = (float4*)(smem + BTILE);
        for (int i = tid; i < BTILE / 16; i += 256) { sh[i] = gh[i]; sl[i] = gl[i]; }
    }
    __syncthreads();
    {
        const float* pa = d_ft + (size_t)last_idx[r0c >> 2] * DIM;
        const float* pb = d_ft + (size_t)last_idx[r1c >> 2] * DIM;
        #pragma unroll
        for (int k16 = 0; k16 < 8; k16++) {
            LOAD_A_FRAGS(pa, pb, k16 * 16 + c0);
            uint32_t koff = (uint32_t)k16 * 32;
            MMA_STRIP(koff);
        }
    }

    #pragma unroll
    for (int t = 0; t < 16; t++) {
        int n = t * 8 + c0;
        if (row0 < N_TGT) *(float2*)&d_f[(size_t)row0 * DIM + n] = make_float2(acc[t][0], acc[t][1]);
        if (row1 < N_TGT) *(float2*)&d_f[(size_t)row1 * DIM + n] = make_float2(acc[t][2], acc[t][3]);
    }
}

// ---------------- K6: mma.sync, A from global regs, B in smem; occupancy 2 ----------------
#define SM_BH   0
#define SM_BL   BTILE
#define SM_SRC  (2 * BTILE)
#define SM_DST  (SM_SRC + 512)
#define SM_S    (SM_DST + 512)
#define SM_TOTAL (SM_S + 512)

__global__ __launch_bounds__(256, 2)
void edge2_mma_kernel(
    const float* __restrict__ h_p,
    const int* __restrict__ src2, const int* __restrict__ dst2,
    float* __restrict__ out)
{
    extern __shared__ __align__(16) char smem[];
    uint32_t sb = smem_to_u32(smem);
    int tid = threadIdx.x;
    int w = tid >> 5;
    int lane = tid & 31;
    int eb = blockIdx.x * 128;

    int* ssrc = (int*)(smem + SM_SRC);
    int* sdst = (int*)(smem + SM_DST);
    float* s_s = (float*)(smem + SM_S);

    if (tid < 128) { ssrc[tid] = src2[eb + tid]; sdst[tid] = dst2[eb + tid]; }

    {
        const float4* gh = (const float4*)d_Bh2;
        const float4* gl = (const float4*)d_Bl2;
        float4* sh = (float4*)(smem + SM_BH);
        float4* sl = (float4*)(smem + SM_BL);
        for (int i = tid; i < BTILE / 16; i += 256) { sh[i] = gh[i]; sl[i] = gl[i]; }
    }
    __syncthreads();

    float acc[16][4];
    #pragma unroll
    for (int t = 0; t < 16; t++)
        #pragma unroll
        for (int j = 0; j < 4; j++) acc[t][j] = 0.0f;

    int qi = lane & 7;
    int quad = lane >> 3;
    uint32_t b_lane = (uint32_t)(qi + ((quad >= 2) ? 8 : 0)) * ROWB + ((quad & 1) ? 16 : 0);
    uint32_t bh_base = sb + SM_BH + b_lane;
    uint32_t bl_base = sb + SM_BL + b_lane;

    const float* pa = h_p + (size_t)(eb + w * 16 + (lane >> 2)) * DIM;
    const float* pb = pa + 8 * DIM;
    int c0 = (lane & 3) * 2;

    #pragma unroll
    for (int k16 = 0; k16 < 8; k16++) {
        LOAD_A_FRAGS(pa, pb, k16 * 16 + c0);
        uint32_t koff = (uint32_t)k16 * 32;
        MMA_STRIP(koff);
    }

    // epilogue: e2 = tanh(acc + g[src]); s = sum(e2 * f[dst])
    {
        int r0 = w * 16 + (lane >> 2);
        int r1 = r0 + 8;
        int src0 = ssrc[r0], dst0 = sdst[r0];
        int src1i = ssrc[r1], dst1i = sdst[r1];
        const float* g0p = d_g + (size_t)src0 * DIM;
        const float* f0p = d_f + (size_t)dst0 * DIM;
        const float* g1p = d_g + (size_t)src1i * DIM;
        const float* f1p = d_f + (size_t)dst1i * DIM;
        float s0 = 0.0f, s1 = 0.0f;
        #pragma unroll
        for (int t = 0; t < 16; t++) {
            int n = t * 8 + c0;
            float2 ga = *(const float2*)(g0p + n);
            float2 fa = *(const float2*)(f0p + n);
            float2 gb = *(const float2*)(g1p + n);
            float2 fb = *(const float2*)(f1p + n);
            s0 += tanh_fast(acc[t][0] + ga.x) * fa.x + tanh_fast(acc[t][1] + ga.y) * fa.y;
            s1 += tanh_fast(acc[t][2] + gb.x) * fb.x + tanh_fast(acc[t][3] + gb.y) * fb.y;
        }
        s0 += __shfl_xor_sync(0xffffffffu, s0, 1);
        s0 += __shfl_xor_sync(0xffffffffu, s0, 2);
        s1 += __shfl_xor_sync(0xffffffffu, s1, 1);
        s1 += __shfl_xor_sync(0xffffffffu, s1, 2);
        if ((lane & 3) == 0) { s_s[r0] = s0; s_s[r1] = s1; }
    }
    __syncthreads();

    // scatter: out[dst2[e]] += ft[src2[e]] * s[e]
    {
        #pragma unroll 4
        for (int r = w * 16; r < w * 16 + 16; r++) {
            float sv = s_s[r];
            float4 v = ((const float4*)(d_ft + (size_t)ssrc[r] * DIM))[lane];
            v.x *= sv; v.y *= sv; v.z *= sv; v.w *= sv;
            red_add_v4(out + (size_t)sdst[r] * DIM + lane * 4, v);
        }
    }
}

// ---------------- launcher ----------------
extern "C" void kernel_launch(void* const* d_in, const int* in_sizes, int n_in,
                              void* d_out, int out_size) {
    const float* h_v  = (const float*)d_in[0];
    const float* h_d  = (const float*)d_in[1];
    const float* h_p  = (const float*)d_in[2];
    const float* h_t  = (const float*)d_in[3];
    const float* W_pi = (const float*)d_in[4];
    const float* W_M  = (const float*)d_in[5];
    const float* W_q  = (const float*)d_in[6];
    const float* W_r  = (const float*)d_in[7];
    const int* src1 = (const int*)d_in[8];
    const int* dst1 = (const int*)d_in[9];
    const int* src2 = (const int*)d_in[10];
    const int* dst2 = (const int*)d_in[11];
    const int* last_idx = (const int*)d_in[12];
    float* out = (float*)d_out;

    cudaFuncSetAttribute(edge2_mma_kernel, cudaFuncAttributeMaxDynamicSharedMemorySize, SM_TOTAL);
    cudaFuncSetAttribute(gemm_g_mma, cudaFuncAttributeMaxDynamicSharedMemorySize, SMG_TOTAL);
    cudaFuncSetAttribute(gemm_f_mma, cudaFuncAttributeMaxDynamicSharedMemorySize, SMG_TOTAL);

    init_kernel<<<2048, 256>>>(out);
    edge1_kernel<<<E1N / 32, 256>>>(h_v, h_d, W_pi, W_M, src1, dst1);
    edge1_softmax_kernel<<<(E1N + 255) / 256, 256>>>(dst1);
    edge1_agg_kernel<<<E1N / 32, 256>>>(h_v, src1, dst1);
    prep_wq_kernel<<<(2 * DIM * DIM + 255) / 256, 256>>>(W_q);
    prep_wr_kernel<<<(2 * DIM * DIM + 255) / 256, 256>>>(W_r);
    gemm_g_mma<<<(N_ITEMS + 127) / 128, 256, SMG_TOTAL>>>();
    gemm_f_mma<<<(N_TGT + 127) / 128, 256, SMG_TOTAL>>>(h_t, last_idx);
    edge2_mma_kernel<<<E2N / 128, 256, SM_TOTAL>>>(h_p, src2, dst2, out);
}